// round 1
// baseline (speedup 1.0000x reference)
#include <cuda_runtime.h>
#include <math.h>

static constexpr int V   = 2048;
static constexpr int VM1 = 2047;   // noise columns
static constexpr float PPROB    = 0.1f;
static constexpr float INV_VM2  = 1.0f / 2046.0f;
static constexpr float LOG_KEEP = -0.10536051565782628f;  // ln(0.9)
static constexpr float LOG_REP  = -9.9262269f;            // ln(0.1/2046)

__global__ __launch_bounds__(256)
void sym_channel_kernel(const float* __restrict__ msgs,
                        const float* __restrict__ logits,
                        const float* __restrict__ noise,
                        float* __restrict__ out,
                        int nrows)
{
    __shared__ float sm_m[V];
    __shared__ float sm_t[V];       // t[c] valid for c in [0, VM1)
    __shared__ float warp_sums[8];
    __shared__ float sh_l0, sh_e0;

    const int r   = blockIdx.x;
    const int tid = threadIdx.x;
    const size_t rowoff = (size_t)r * V;
    const size_t N      = (size_t)nrows * V;

    const float4* m4 = reinterpret_cast<const float4*>(msgs + rowoff);
    const float4* l4 = reinterpret_cast<const float4*>(logits + rowoff);
    const float*  nrow = noise + (size_t)r * VM1;

    float4* out_m4  = reinterpret_cast<float4*>(out + rowoff);            // m_noisy
    float4* out_l4  = reinterpret_cast<float4*>(out + N + rowoff);        // logits_noisy
    float4* out_mc4 = reinterpret_cast<float4*>(out + 2 * N + rowoff);    // messages copy
    float4* out_lc4 = reinterpret_cast<float4*>(out + 3 * N + rowoff);    // logits copy

    if (tid == 0) {
        float l0 = logits[rowoff];
        sh_l0 = l0;
        sh_e0 = expf(l0);
    }

    // ---- Pass 1: load messages, write copy, compute t + partial row sum ----
    float lsum = 0.0f;
    #pragma unroll
    for (int k = 0; k < 2; k++) {
        int i4 = tid + k * 256;                 // 0..511
        float4 v = m4[i4];
        reinterpret_cast<float4*>(sm_m)[i4] = v;
        out_mc4[i4] = v;
        float mv[4] = {v.x, v.y, v.z, v.w};
        int base = i4 * 4;
        #pragma unroll
        for (int j = 0; j < 4; j++) {
            int c = base + j;
            if (c < VM1) {
                float t = (nrow[c] < PPROB) ? mv[j] : 0.0f;
                sm_t[c] = t;
                lsum += t;
            }
        }
    }

    // ---- Block reduction of row sum ----
    #pragma unroll
    for (int off = 16; off > 0; off >>= 1)
        lsum += __shfl_down_sync(0xFFFFFFFFu, lsum, off);
    if ((tid & 31) == 0) warp_sums[tid >> 5] = lsum;
    __syncthreads();

    float row_sum = 0.0f;
    #pragma unroll
    for (int w = 0; w < 8; w++) row_sum += warp_sums[w];

    const float add_c = row_sum * INV_VM2;
    const float scale = 1.0f + INV_VM2;

    // ---- Pass 2: m_noisy (needs neighbor t[j-1] from smem) ----
    #pragma unroll
    for (int k = 0; k < 2; k++) {
        int i4 = tid + k * 256;
        int base = i4 * 4;
        float4 o;
        float* op = &o.x;
        #pragma unroll
        for (int j = 0; j < 4; j++) {
            int jj = base + j;
            float val = sm_m[jj];
            if (jj > 0)
                val += add_c - sm_t[jj - 1] * scale;
            op[j] = val;
        }
        out_m4[i4] = o;
    }

    // ---- Pass 3: logits copy + noisy logits (elementwise given l0/e0) ----
    const float l0 = sh_l0;
    const float e0 = sh_e0;
    #pragma unroll
    for (int k = 0; k < 2; k++) {
        int i4 = tid + k * 256;
        float4 lv = l4[i4];
        out_lc4[i4] = lv;
        float in[4] = {lv.x, lv.y, lv.z, lv.w};
        float4 o;
        float* op = &o.x;
        int base = i4 * 4;
        #pragma unroll
        for (int j = 0; j < 4; j++) {
            int jj = base + j;
            if (jj == 0) { op[j] = l0; continue; }
            float lj = in[j];
            float pt = 1.0f - expf(lj) - e0;
            pt = fminf(fmaxf(pt, 0.0f), 1.0f);
            float a = lj + LOG_KEEP;
            float b = logf(pt) + LOG_REP;       // logf(0) = -inf is fine
            float mx = fmaxf(a, b);
            float mn = fminf(a, b);
            op[j] = mx + log1pf(expf(mn - mx)); // exp(-inf)=0 -> mx
        }
        out_l4[i4] = o;
    }
}

extern "C" void kernel_launch(void* const* d_in, const int* in_sizes, int n_in,
                              void* d_out, int out_size)
{
    const float* msgs   = (const float*)d_in[0];
    const float* logits = (const float*)d_in[1];
    const float* noise  = (const float*)d_in[2];
    float* out = (float*)d_out;
    int nrows = in_sizes[0] / V;   // 16384
    sym_channel_kernel<<<nrows, 256>>>(msgs, logits, noise, out, nrows);
}